// round 1
// baseline (speedup 1.0000x reference)
#include <cuda_runtime.h>

// TreeModel: depth-14 perfect binary heap over 32767 nodes, 16384 leaves, dim 512.
// out[0..16383] = result[i] = dot(x[i], sum of deltas along root->leaf path)
// out[16384]    = sq[0] + sum_{n>=1} sq[n] / max(heights[n]-heights[parent], 1e-7)
//
// Strategy:
//  - main_kernel: 1024 CTAs (one per level-10 subtree), 512 threads.
//      Phase 1: SMEM wp[512] = sum of 11 ancestor rows (levels 0..10), coalesced.
//      Phase 2: each of 16 warps owns one leaf; adds its private level-11..14 rows
//               (float4 loads), fuses squared-sum for rows it uniquely owns,
//               then dots with x row. Every delta/x byte read once from DRAM.
//  - upper_sq_kernel: sq contributions for nodes 0..2046 (levels 0..10).
//  - final_kernel: deterministic fixed-order reduction of all partials.
// No atomics anywhere -> bitwise deterministic across replays.

#define DIM 512
#define N_LEAVES 16384

__device__ float g_part0[2048];   // per-node contributions, nodes 0..2046 (+pad)
__device__ float g_partB[1024];   // per-CTA contributions, levels 11..14

__device__ __forceinline__ float warp_sum(float v) {
#pragma unroll
    for (int o = 16; o > 0; o >>= 1) v += __shfl_down_sync(0xffffffffu, v, o);
    return v;
}

// ---------------- sq contributions for nodes 0..2046 (levels 0..10) -------------
__global__ __launch_bounds__(1024) void upper_sq_kernel(const float* __restrict__ deltas,
                                                        const float* __restrict__ heights) {
    int gw   = blockIdx.x * 32 + (threadIdx.x >> 5);   // global warp id = node id
    int lane = threadIdx.x & 31;
    if (gw >= 2047) {                                   // pad slot -> 0
        if (lane == 0 && gw < 2048) g_part0[gw] = 0.f;
        return;
    }
    const float4* row = (const float4*)(deltas + (size_t)gw * DIM);
    float sqa = 0.f;
#pragma unroll
    for (int k = 0; k < 4; ++k) {
        float4 v = row[k * 32 + lane];
        sqa = fmaf(v.x, v.x, sqa); sqa = fmaf(v.y, v.y, sqa);
        sqa = fmaf(v.z, v.z, sqa); sqa = fmaf(v.w, v.w, sqa);
    }
    sqa = warp_sum(sqa);
    if (lane == 0) {
        float c;
        if (gw == 0) {
            c = sqa;
        } else {
            float br = fmaxf(heights[gw] - heights[(gw - 1) >> 1], 1e-7f);
            c = sqa / br;
        }
        g_part0[gw] = c;
    }
}

// ---------------- main: results + sq for levels 11..14 -------------------------
__global__ __launch_bounds__(512) void main_kernel(const float* __restrict__ x,
                                                   const float* __restrict__ deltas,
                                                   const float* __restrict__ heights,
                                                   float* __restrict__ out) {
    __shared__ float wp[DIM];        // partial weight: sum of levels 0..10 ancestors
    __shared__ float slab[16 * 4];   // per-warp per-level sq contributions

    const int bid  = blockIdx.x;     // level-10 subtree id, 0..1023
    const int tid  = threadIdx.x;
    const int w    = tid >> 5;       // warp = local leaf 0..15
    const int lane = tid & 31;

    if (tid < 64) slab[tid] = 0.f;

    // Phase 1: shared partial weight along root -> level-10 subtree root.
    {
        int anc[11];
        anc[10] = 1023 + bid;                       // level-10 node
#pragma unroll
        for (int l = 10; l > 0; --l) anc[l - 1] = (anc[l] - 1) >> 1;
        float s = 0.f;
#pragma unroll
        for (int l = 0; l < 11; ++l) s += deltas[(size_t)anc[l] * DIM + tid];
        wp[tid] = s;
    }
    __syncthreads();

    // Phase 2: one warp per leaf.
    const int leaf = bid * 16 + w;
    int nodes[4];                                    // levels 11,12,13,14 ancestors
    nodes[3] = (N_LEAVES - 1) + leaf;                // level-14 leaf node
#pragma unroll
    for (int l = 3; l > 0; --l) nodes[l - 1] = (nodes[l] - 1) >> 1;

    float4 wa[4];
    const float4* wp4 = (const float4*)wp;
#pragma unroll
    for (int k = 0; k < 4; ++k) wa[k] = wp4[k * 32 + lane];

#pragma unroll
    for (int L = 0; L < 4; ++L) {                    // level 11+L
        const float4* row = (const float4*)(deltas + (size_t)nodes[L] * DIM);
        const bool owner = ((w & ((1 << (3 - L)) - 1)) == 0);  // leftmost leaf under node
        float sqa = 0.f;
#pragma unroll
        for (int k = 0; k < 4; ++k) {
            float4 v = row[k * 32 + lane];
            wa[k].x += v.x; wa[k].y += v.y; wa[k].z += v.z; wa[k].w += v.w;
            sqa = fmaf(v.x, v.x, sqa); sqa = fmaf(v.y, v.y, sqa);
            sqa = fmaf(v.z, v.z, sqa); sqa = fmaf(v.w, v.w, sqa);
        }
        if (owner) {
            sqa = warp_sum(sqa);
            if (lane == 0) {
                int n = nodes[L];
                float br = fmaxf(heights[n] - heights[(n - 1) >> 1], 1e-7f);
                slab[w * 4 + L] = sqa / br;
            }
        }
    }

    // Dot with x row.
    const float4* xr = (const float4*)(x + (size_t)leaf * DIM);
    float acc = 0.f;
#pragma unroll
    for (int k = 0; k < 4; ++k) {
        float4 xv = xr[k * 32 + lane];
        acc = fmaf(xv.x, wa[k].x, acc);
        acc = fmaf(xv.y, wa[k].y, acc);
        acc = fmaf(xv.z, wa[k].z, acc);
        acc = fmaf(xv.w, wa[k].w, acc);
    }
    acc = warp_sum(acc);
    if (lane == 0) out[leaf] = acc;

    // Deterministic CTA reduction of the 64 sq slots.
    __syncthreads();
    if (w == 0) {
        float s = 0.f;
        if (lane < 16) {
#pragma unroll
            for (int j = 0; j < 4; ++j) s += slab[lane * 4 + j];
        }
        s = warp_sum(s);
        if (lane == 0) g_partB[bid] = s;
    }
}

// ---------------- final deterministic reduction --------------------------------
__global__ __launch_bounds__(1024) void final_kernel(float* __restrict__ out) {
    __shared__ float sm[32];
    const int tid = threadIdx.x;
    float s = 0.f;
#pragma unroll
    for (int r = 0; r < 3; ++r) {                    // 3072 values total, fixed order
        int i = tid + r * 1024;
        s += (i < 2048) ? g_part0[i] : g_partB[i - 2048];
    }
    s = warp_sum(s);
    if ((tid & 31) == 0) sm[tid >> 5] = s;
    __syncthreads();
    if (tid < 32) {
        float v = sm[tid];
        v = warp_sum(v);
        if (tid == 0) out[N_LEAVES] = v;
    }
}

extern "C" void kernel_launch(void* const* d_in, const int* in_sizes, int n_in,
                              void* d_out, int out_size) {
    const float* x       = (const float*)d_in[0];
    const float* deltas  = (const float*)d_in[1];
    const float* heights = (const float*)d_in[2];
    float* out = (float*)d_out;

    upper_sq_kernel<<<64, 1024>>>(deltas, heights);
    main_kernel<<<1024, 512>>>(x, deltas, heights, out);
    final_kernel<<<1, 1024>>>(out);
}

// round 2
// speedup vs baseline: 1.0755x; 1.0755x over previous
#include <cuda_runtime.h>

// TreeModel: depth-14 perfect binary heap, 32767 nodes, 16384 leaves, dim 512.
// out[0..16383] = dot(x[i], sum of deltas along root->leaf path)
// out[16384]    = sq[0] + sum_{n>=1} sq[n] / max(heights[n]-heights[parent], 1e-7)
//
// Single fused kernel, 1024 CTAs (one per level-10 subtree) x 512 threads.
//  - Phase 1 (per-thread column): running sum over the 11 ancestors (levels 0..10).
//    Owner-CTA trick folds the upper-node sq/branch terms into a per-thread
//    accumulator: sum_n sq[n]/br_n == sum_d sum_n delta^2 * inv_br  (reorderable).
//  - Levels 11..13 expand in registers (c11[2], c12[4]) then SMEM s13[8][512];
//    every delta row is read from DRAM/L2 exactly once.
//  - Level 14: one warp per leaf; float4 loads of leaf delta row + x row,
//    sq fused, dot -> out[leaf].
//  - delta_total: per-thread sqacc -> CTA reduce -> g_part[bid];
//    threadfence+counter, last CTA reduces 1024 partials in fixed order.
// No per-value atomics -> bitwise deterministic.

#define DIM 512
#define N_LEAVES 16384
#define NCTA 1024

__device__ float g_part[NCTA];
__device__ unsigned int g_count = 0;

__device__ __forceinline__ float warp_sum(float v) {
#pragma unroll
    for (int o = 16; o > 0; o >>= 1) v += __shfl_down_sync(0xffffffffu, v, o);
    return v;
}

__device__ __forceinline__ float inv_branch(const float* __restrict__ heights, int n) {
    // n > 0
    return 1.0f / fmaxf(heights[n] - heights[(n - 1) >> 1], 1e-7f);
}

__global__ __launch_bounds__(512) void tree_kernel(const float* __restrict__ x,
                                                   const float* __restrict__ deltas,
                                                   const float* __restrict__ heights,
                                                   float* __restrict__ out) {
    __shared__ float s13[8 * DIM];   // level-13 weight columns (16 KB)
    __shared__ float red[16];
    __shared__ int   is_last;

    const int bid  = blockIdx.x;     // level-10 subtree id
    const int tid  = threadIdx.x;
    const int w    = tid >> 5;       // warp = local leaf 0..15
    const int lane = tid & 31;

    float sqacc = 0.f;               // per-thread partial of delta_total

    // ---------- Phase 1: levels 0..10 (per-thread column, no sync needed) ----
    const int n10 = 1023 + bid;
    float c10;
    {
        int anc[11];
        anc[10] = n10;
#pragma unroll
        for (int l = 10; l > 0; --l) anc[l - 1] = (anc[l] - 1) >> 1;
        float s = 0.f;
#pragma unroll
        for (int l = 0; l <= 10; ++l) {
            float v = deltas[(size_t)anc[l] * DIM + tid];
            s += v;
            // owner-CTA for the level-l ancestor: leftmost subtree beneath it
            if ((bid & ((1 << (10 - l)) - 1)) == 0) {
                int   n   = anc[l];
                float inv = (n == 0) ? 1.0f : inv_branch(heights, n);
                sqacc = fmaf(v * v, inv, sqacc);
            }
        }
        c10 = s;
    }

    // ---------- Levels 11..13: expand columns (still per-thread, no sync) ----
    const int b11 = 2 * n10 + 1;     // first level-11 child
    const int b12 = 2 * b11 + 1;
    const int b13 = 2 * b12 + 1;

    float c11[2];
#pragma unroll
    for (int j = 0; j < 2; ++j) {
        int   n = b11 + j;
        float v = deltas[(size_t)n * DIM + tid];
        sqacc = fmaf(v * v, inv_branch(heights, n), sqacc);
        c11[j] = c10 + v;
    }
    float c12[4];
#pragma unroll
    for (int j = 0; j < 4; ++j) {
        int   n = b12 + j;
        float v = deltas[(size_t)n * DIM + tid];
        sqacc = fmaf(v * v, inv_branch(heights, n), sqacc);
        c12[j] = c11[j >> 1] + v;
    }
#pragma unroll
    for (int j = 0; j < 8; ++j) {
        int   n = b13 + j;
        float v = deltas[(size_t)n * DIM + tid];
        sqacc = fmaf(v * v, inv_branch(heights, n), sqacc);
        s13[j * DIM + tid] = c12[j >> 1] + v;
    }
    __syncthreads();                 // s13 columns complete

    // ---------- Level 14: one warp per leaf ---------------------------------
    const int leaf = bid * 16 + w;
    const int n14  = (N_LEAVES - 1) + leaf;
    const float inv14 = inv_branch(heights, n14);

    const float4* wp4 = (const float4*)(s13 + (size_t)(w >> 1) * DIM);
    const float4* dr  = (const float4*)(deltas + (size_t)n14 * DIM);
    const float4* xr  = (const float4*)(x + (size_t)leaf * DIM);

    float acc = 0.f;
#pragma unroll
    for (int k = 0; k < 4; ++k) {
        float4 wv = wp4[k * 32 + lane];
        float4 dv = dr[k * 32 + lane];
        float4 xv = xr[k * 32 + lane];
        sqacc = fmaf(dv.x, dv.x * inv14, sqacc);
        sqacc = fmaf(dv.y, dv.y * inv14, sqacc);
        sqacc = fmaf(dv.z, dv.z * inv14, sqacc);
        sqacc = fmaf(dv.w, dv.w * inv14, sqacc);
        acc = fmaf(xv.x, wv.x + dv.x, acc);
        acc = fmaf(xv.y, wv.y + dv.y, acc);
        acc = fmaf(xv.z, wv.z + dv.z, acc);
        acc = fmaf(xv.w, wv.w + dv.w, acc);
    }
    acc = warp_sum(acc);
    if (lane == 0) out[leaf] = acc;

    // ---------- CTA reduction of sqacc --------------------------------------
    sqacc = warp_sum(sqacc);
    if (lane == 0) red[w] = sqacc;
    __syncthreads();
    if (tid == 0) {
        float t = 0.f;
#pragma unroll
        for (int j = 0; j < 16; ++j) t += red[j];
        g_part[bid] = t;
        __threadfence();
        unsigned prev = atomicAdd(&g_count, 1u);
        is_last = (prev == NCTA - 1) ? 1 : 0;
    }
    __syncthreads();

    // ---------- Last CTA: deterministic final reduction ---------------------
    if (is_last) {
        const volatile float* gp = g_part;
        float s = gp[tid] + gp[tid + 512];
        s = warp_sum(s);
        if (lane == 0) red[w] = s;
        __syncthreads();
        if (tid == 0) {
            float t = 0.f;
#pragma unroll
            for (int j = 0; j < 16; ++j) t += red[j];
            out[N_LEAVES] = t;
            g_count = 0;             // reset for next graph replay
        }
    }
}

extern "C" void kernel_launch(void* const* d_in, const int* in_sizes, int n_in,
                              void* d_out, int out_size) {
    const float* x       = (const float*)d_in[0];
    const float* deltas  = (const float*)d_in[1];
    const float* heights = (const float*)d_in[2];
    float* out = (float*)d_out;

    tree_kernel<<<NCTA, 512>>>(x, deltas, heights, out);
}

// round 3
// speedup vs baseline: 1.0935x; 1.0168x over previous
#include <cuda_runtime.h>

// TreeModel: depth-14 perfect binary heap, 32767 nodes, 16384 leaves, dim 512.
// out[0..16383] = dot(x[i], sum of deltas along root->leaf path)
// out[16384]    = sq[0] + sum_{n>=1} sq[n]/max(heights[n]-heights[parent],1e-7)
//
// 2048 CTAs (one per level-11 subtree) x 256 threads, everything LDG.128:
//  - Phase 1: 2 thread-groups split the 12 upper rows (levels 0..11, 6 float4
//    loads each), exchange partials through 4KB SMEM (single sync).
//    Owner-CTA trick folds upper sq/branch terms in during the load.
//  - Phase 2: slice s (128 threads) owns level-12 node s: loads its level-12
//    row, 2 level-13 rows, 4 leaf rows, 4 x rows -- 11 independent LDG.128 per
//    thread, weights held in registers. sq terms fused.
//  - result reduction: per-leaf dot partials reduced via shfl + tiny SMEM.
//  - delta_total: per-thread sqacc -> CTA value -> g_part[bid]; last-CTA
//    (fence+counter) reduces 2048 partials in fixed order. Deterministic.

#define DIM 512
#define N_LEAVES 16384
#define NCTA 2048

__device__ float g_part[NCTA];
__device__ unsigned int g_count = 0;

__device__ __forceinline__ float warp_sum(float v) {
#pragma unroll
    for (int o = 16; o > 0; o >>= 1) v += __shfl_down_sync(0xffffffffu, v, o);
    return v;
}

__device__ __forceinline__ float inv_branch(const float* __restrict__ heights, int n) {
    return 1.0f / fmaxf(heights[n] - heights[(n - 1) >> 1], 1e-7f);
}

__device__ __forceinline__ float sq4(float4 v) {
    return fmaf(v.x, v.x, fmaf(v.y, v.y, fmaf(v.z, v.z, v.w * v.w)));
}

__global__ __launch_bounds__(256) void tree_kernel(const float* __restrict__ x,
                                                   const float* __restrict__ deltas,
                                                   const float* __restrict__ heights,
                                                   float* __restrict__ out) {
    __shared__ float4 sp[2][128];    // phase-1 partial columns (4 KB)
    __shared__ float redL[32];       // 8 leaves x 4 warps-in-slice
    __shared__ float redS[8];        // sq per warp
    __shared__ int   is_last;

    const int bid  = blockIdx.x;     // level-11 subtree id
    const int tid  = threadIdx.x;
    const int col  = tid & 127;      // float4 column within row
    const int g    = tid >> 7;       // slice 0/1
    const int w    = tid >> 5;       // warp 0..7
    const int lane = tid & 31;

    float sqacc = 0.f;

    // ---------- ancestors (levels 0..11) ------------------------------------
    const int n11 = 2047 + bid;
    int anc[12];
    anc[11] = n11;
#pragma unroll
    for (int l = 11; l > 0; --l) anc[l - 1] = (anc[l] - 1) >> 1;

    // ---------- Phase 1: split 12 upper rows across the 2 slices ------------
    float4 s = make_float4(0.f, 0.f, 0.f, 0.f);
#pragma unroll
    for (int l = 0; l <= 11; ++l) {
        if ((l & 1) == g) {
            const float4* row = (const float4*)(deltas + (size_t)anc[l] * DIM);
            float4 v = row[col];
            s.x += v.x; s.y += v.y; s.z += v.z; s.w += v.w;
            if ((bid & ((1 << (11 - l)) - 1)) == 0) {   // owner CTA for this node
                float inv = (l == 0) ? 1.0f : inv_branch(heights, anc[l]);
                sqacc = fmaf(sq4(v), inv, sqacc);
            }
        }
    }
    sp[g][col] = s;
    __syncthreads();
    float4 a = sp[0][col], b = sp[1][col];
    float4 c11 = make_float4(a.x + b.x, a.y + b.y, a.z + b.z, a.w + b.w);

    // ---------- Phase 2: slice owns level-12 node g -------------------------
    const int n12 = 2 * n11 + 1 + g;
    {
        const float4* row = (const float4*)(deltas + (size_t)n12 * DIM);
        float4 v = row[col];
        sqacc = fmaf(sq4(v), inv_branch(heights, n12), sqacc);
        c11.x += v.x; c11.y += v.y; c11.z += v.z; c11.w += v.w;   // c11 -> c12
    }
    const int n13b = 2 * n12 + 1;
    float4 c13[2];
#pragma unroll
    for (int j = 0; j < 2; ++j) {
        const int n = n13b + j;
        const float4* row = (const float4*)(deltas + (size_t)n * DIM);
        float4 v = row[col];
        sqacc = fmaf(sq4(v), inv_branch(heights, n), sqacc);
        c13[j] = make_float4(c11.x + v.x, c11.y + v.y, c11.z + v.z, c11.w + v.w);
    }

    const int leaf0 = bid * 8 + g * 4;
    float acc[4];
#pragma unroll
    for (int j = 0; j < 4; ++j) {
        const int n = (N_LEAVES - 1) + leaf0 + j;
        const float4* dr = (const float4*)(deltas + (size_t)n * DIM);
        const float4* xr = (const float4*)(x + (size_t)(leaf0 + j) * DIM);
        float4 dv = dr[col];
        float4 xv = xr[col];
        sqacc = fmaf(sq4(dv), inv_branch(heights, n), sqacc);
        float4 wv = c13[j >> 1];
        float t;
        t  = xv.x * (wv.x + dv.x);
        t  = fmaf(xv.y, wv.y + dv.y, t);
        t  = fmaf(xv.z, wv.z + dv.z, t);
        t  = fmaf(xv.w, wv.w + dv.w, t);
        acc[j] = t;
    }

    // ---------- result reduction: 128 threads per leaf ----------------------
#pragma unroll
    for (int j = 0; j < 4; ++j) acc[j] = warp_sum(acc[j]);
    if (lane == 0) {
        const int ws = w & 3;                 // warp within slice
#pragma unroll
        for (int j = 0; j < 4; ++j) redL[(g * 4 + j) * 4 + ws] = acc[j];
    }

    // ---------- sq reduction -------------------------------------------------
    sqacc = warp_sum(sqacc);
    if (lane == 0) redS[w] = sqacc;
    __syncthreads();

    if (tid < 8) {
        float r = redL[tid * 4] + redL[tid * 4 + 1] + redL[tid * 4 + 2] + redL[tid * 4 + 3];
        out[bid * 8 + tid] = r;
    }
    if (tid == 0) {
        float t = 0.f;
#pragma unroll
        for (int j = 0; j < 8; ++j) t += redS[j];
        g_part[bid] = t;
        __threadfence();
        unsigned prev = atomicAdd(&g_count, 1u);
        is_last = (prev == NCTA - 1) ? 1 : 0;
    }
    __syncthreads();

    // ---------- last CTA: deterministic final reduction ---------------------
    if (is_last) {
        const volatile float* gp = g_part;
        float sm = 0.f;
#pragma unroll
        for (int r = 0; r < 8; ++r) sm += gp[tid + 256 * r];
        sm = warp_sum(sm);
        if (lane == 0) redS[w] = sm;
        __syncthreads();
        if (tid == 0) {
            float t = 0.f;
#pragma unroll
            for (int j = 0; j < 8; ++j) t += redS[j];
            out[N_LEAVES] = t;
            g_count = 0;             // reset for next graph replay
        }
    }
}

extern "C" void kernel_launch(void* const* d_in, const int* in_sizes, int n_in,
                              void* d_out, int out_size) {
    const float* x       = (const float*)d_in[0];
    const float* deltas  = (const float*)d_in[1];
    const float* heights = (const float*)d_in[2];
    float* out = (float*)d_out;

    tree_kernel<<<NCTA, 256>>>(x, deltas, heights, out);
}

// round 4
// speedup vs baseline: 1.1530x; 1.0544x over previous
#include <cuda_runtime.h>
#include <cstdint>

// TreeModel: depth-14 perfect binary heap, 32767 nodes, 16384 leaves, dim 512.
// out[0..16383] = dot(x[i], sum of deltas along root->leaf path)
// out[16384]    = sq[0] + sum_{n>=1} sq[n]/max(heights[n]-heights[parent],1e-7)
//
// 2048 CTAs (one per level-11 subtree) x 256 threads.
//  - At CTA start, one thread issues two cp.async.bulk (UBLKCP) copies:
//    the 8 leaf-delta rows (16KB) and the 8 x rows (16KB) -> SMEM, tracked by
//    one mbarrier (expect_tx 32KB). Bulk loads carry no register pressure and
//    put all streaming bytes in flight immediately.
//  - While the bulk is in flight: levels 0..11 (L2-hot) via slice-split LDG.128
//    + 4KB SMEM exchange; level-12/level-13 unique rows via LDG.128.
//    Owner-CTA trick folds all sq/branch terms into a per-thread accumulator.
//  - After mbarrier: leaf weights + dots entirely from SMEM (LDS.128).
//  - delta_total: CTA reduce -> g_part[bid]; fence+counter last-CTA reduces
//    2048 partials in fixed order. No data atomics -> deterministic.

#define DIM 512
#define N_LEAVES 16384
#define NCTA 2048

__device__ float g_part[NCTA];
__device__ unsigned int g_count = 0;

__device__ __forceinline__ float warp_sum(float v) {
#pragma unroll
    for (int o = 16; o > 0; o >>= 1) v += __shfl_down_sync(0xffffffffu, v, o);
    return v;
}

__device__ __forceinline__ float inv_branch(const float* __restrict__ heights, int n) {
    return 1.0f / fmaxf(heights[n] - heights[(n - 1) >> 1], 1e-7f);
}

__device__ __forceinline__ float sq4(float4 v) {
    return fmaf(v.x, v.x, fmaf(v.y, v.y, fmaf(v.z, v.z, v.w * v.w)));
}

__global__ __launch_bounds__(256, 5) void tree_kernel(const float* __restrict__ x,
                                                      const float* __restrict__ deltas,
                                                      const float* __restrict__ heights,
                                                      float* __restrict__ out) {
    __shared__ float4 dl[8][128];     // leaf delta rows (16 KB)
    __shared__ float4 xs[8][128];     // x rows          (16 KB)
    __shared__ float4 sp[2][128];     // phase-1 exchange (4 KB)
    __shared__ float  redL[32];
    __shared__ float  redS[8];
    __shared__ int    is_last;
    __shared__ __align__(8) unsigned long long mbar;

    const int bid  = blockIdx.x;      // level-11 subtree id
    const int tid  = threadIdx.x;
    const int col  = tid & 127;       // float4 column
    const int g    = tid >> 7;        // slice 0/1
    const int w    = tid >> 5;        // warp 0..7
    const int lane = tid & 31;

    // ---------------- bulk-async the streaming blocks -----------------------
    const unsigned mb = (unsigned)__cvta_generic_to_shared(&mbar);
    if (tid == 0) {
        asm volatile("mbarrier.init.shared.b64 [%0], %1;" :: "r"(mb), "r"(1));
        asm volatile("fence.proxy.async.shared::cta;" ::: "memory");
        asm volatile("mbarrier.arrive.expect_tx.shared.b64 _, [%0], %1;"
                     :: "r"(mb), "r"(32768u));
        const unsigned d_dl = (unsigned)__cvta_generic_to_shared(&dl[0][0]);
        const unsigned d_xs = (unsigned)__cvta_generic_to_shared(&xs[0][0]);
        const float* src_dl = deltas + (size_t)(N_LEAVES - 1 + 8 * bid) * DIM;
        const float* src_xs = x + (size_t)(8 * bid) * DIM;
        asm volatile("cp.async.bulk.shared::cta.global.mbarrier::complete_tx::bytes "
                     "[%0], [%1], %2, [%3];"
                     :: "r"(d_dl), "l"(src_dl), "r"(16384u), "r"(mb) : "memory");
        asm volatile("cp.async.bulk.shared::cta.global.mbarrier::complete_tx::bytes "
                     "[%0], [%1], %2, [%3];"
                     :: "r"(d_xs), "l"(src_xs), "r"(16384u), "r"(mb) : "memory");
    }

    float sqacc = 0.f;

    // ---------------- ancestors (levels 0..11) ------------------------------
    const int n11 = 2047 + bid;
    int anc[12];
    anc[11] = n11;
#pragma unroll
    for (int l = 11; l > 0; --l) anc[l - 1] = (anc[l] - 1) >> 1;

    // ---------------- upper levels: slice-split LDG (L2-hot) ----------------
    float4 s = make_float4(0.f, 0.f, 0.f, 0.f);
#pragma unroll
    for (int l = 0; l <= 11; ++l) {
        if ((l & 1) == g) {
            const float4* row = (const float4*)(deltas + (size_t)anc[l] * DIM);
            float4 v = row[col];
            s.x += v.x; s.y += v.y; s.z += v.z; s.w += v.w;
            if ((bid & ((1 << (11 - l)) - 1)) == 0) {       // owner CTA
                float inv = (l == 0) ? 1.0f : inv_branch(heights, anc[l]);
                sqacc = fmaf(sq4(v), inv, sqacc);
            }
        }
    }
    sp[g][col] = s;
    __syncthreads();                  // also orders mbarrier.init for all threads
    float4 a = sp[0][col], b = sp[1][col];
    float4 c12 = make_float4(a.x + b.x, a.y + b.y, a.z + b.z, a.w + b.w);

    // ---------------- unique level-12 / level-13 rows via LDG ---------------
    const int n12 = 4095 + 2 * bid + g;
    {
        const float4* row = (const float4*)(deltas + (size_t)n12 * DIM);
        float4 v = row[col];
        sqacc = fmaf(sq4(v), inv_branch(heights, n12), sqacc);
        c12.x += v.x; c12.y += v.y; c12.z += v.z; c12.w += v.w;
    }
    const int n13b = 2 * n12 + 1;
    float4 c13[2];
#pragma unroll
    for (int j = 0; j < 2; ++j) {
        const int n = n13b + j;
        const float4* row = (const float4*)(deltas + (size_t)n * DIM);
        float4 v = row[col];
        sqacc = fmaf(sq4(v), inv_branch(heights, n), sqacc);
        c13[j] = make_float4(c12.x + v.x, c12.y + v.y, c12.z + v.z, c12.w + v.w);
    }

    // ---------------- wait for bulk data ------------------------------------
    asm volatile(
        "{\n\t"
        ".reg .pred p;\n\t"
        "WAIT_%=:\n\t"
        "mbarrier.try_wait.parity.acquire.cta.shared::cta.b64 p, [%0], 0;\n\t"
        "@!p bra WAIT_%=;\n\t"
        "}" :: "r"(mb) : "memory");

    // ---------------- leaves from SMEM --------------------------------------
    float acc[4];
#pragma unroll
    for (int j = 0; j < 4; ++j) {
        const int li = 4 * g + j;                       // local leaf 0..7
        const int n  = (N_LEAVES - 1) + 8 * bid + li;
        float4 dv = dl[li][col];
        float4 xv = xs[li][col];
        sqacc = fmaf(sq4(dv), inv_branch(heights, n), sqacc);
        float4 wv = c13[j >> 1];
        float t;
        t = xv.x * (wv.x + dv.x);
        t = fmaf(xv.y, wv.y + dv.y, t);
        t = fmaf(xv.z, wv.z + dv.z, t);
        t = fmaf(xv.w, wv.w + dv.w, t);
        acc[j] = t;
    }

    // ---------------- result reduction --------------------------------------
#pragma unroll
    for (int j = 0; j < 4; ++j) acc[j] = warp_sum(acc[j]);
    if (lane == 0) {
        const int ws = w & 3;
#pragma unroll
        for (int j = 0; j < 4; ++j) redL[(g * 4 + j) * 4 + ws] = acc[j];
    }

    sqacc = warp_sum(sqacc);
    if (lane == 0) redS[w] = sqacc;
    __syncthreads();

    if (tid < 8) {
        float r = redL[tid * 4] + redL[tid * 4 + 1] + redL[tid * 4 + 2] + redL[tid * 4 + 3];
        out[bid * 8 + tid] = r;
    }
    if (tid == 0) {
        float t = 0.f;
#pragma unroll
        for (int j = 0; j < 8; ++j) t += redS[j];
        g_part[bid] = t;
        __threadfence();
        unsigned prev = atomicAdd(&g_count, 1u);
        is_last = (prev == NCTA - 1) ? 1 : 0;
    }
    __syncthreads();

    // ---------------- last CTA: deterministic final reduction ---------------
    if (is_last) {
        const volatile float* gp = g_part;
        float sm = 0.f;
#pragma unroll
        for (int r = 0; r < 8; ++r) sm += gp[tid + 256 * r];
        sm = warp_sum(sm);
        if (lane == 0) redS[w] = sm;
        __syncthreads();
        if (tid == 0) {
            float t = 0.f;
#pragma unroll
            for (int j = 0; j < 8; ++j) t += redS[j];
            out[N_LEAVES] = t;
            g_count = 0;              // reset for next graph replay
        }
    }
}

extern "C" void kernel_launch(void* const* d_in, const int* in_sizes, int n_in,
                              void* d_out, int out_size) {
    const float* x       = (const float*)d_in[0];
    const float* deltas  = (const float*)d_in[1];
    const float* heights = (const float*)d_in[2];
    float* out = (float*)d_out;

    tree_kernel<<<NCTA, 256>>>(x, deltas, heights, out);
}